// round 15
// baseline (speedup 1.0000x reference)
#include <cuda_runtime.h>
#include <stdint.h>

#define BB 8
#define LL 512
#define CC 6
#define NTOT (BB * LL)     // 4096
#define KK 9
#define BIGF 1e10f
#define PENF 1e19f
#define MARKBITS 0x7F7FFFFFu  // FLT_MAX bits: d^2-space marker for masked entries

#define ROWS_PB 16
#define NBLK 128                // 8 graphs x 16 blocks; all co-resident (1 block/SM)
#define NTHR 1024               // 32 warps
#define CPL 8
#define BPG 16                  // blocks per graph

typedef unsigned long long u64;
typedef unsigned int u32;

// 8MB scratch: clamped-d^2 bits matrix, M[i][j] for i,j in same graph
__device__ u32 g_M[(size_t)NTOT * LL];
// per-graph monotonic ticket counters (never reset; 2^32 % 16 == 0 -> replay-safe)
__device__ u32 g_gcnt[BB];

__global__ __launch_bounds__(NTHR, 1)
void knn_fused_kernel(const float* __restrict__ X,
                      const int*   __restrict__ AP,
                      const int*   __restrict__ S,
                      const int*   __restrict__ SEC,
                      float*       __restrict__ out)
{
    // Column data: [group][ch][lane] float4 {2x, 2y, 2z, |x|^2 + (pad|BOS)*1e19}
    __shared__ float4 s_col[(LL / 32) * CC * 32];          // 48KB
    __shared__ u64 s_res[ROWS_PB][2][KK];

    const int tid  = threadIdx.x;
    const int bid  = blockIdx.x;          // 0..127
    const int lane = tid & 31;
    const int w    = tid >> 5;
    const int rw   = w >> 1;              // row slot (0..15)
    const int h    = w & 1;               // group-parity / column-half
    const int g    = bid >> 4;            // graph
    const int gbase = g << 9;

    // ---- constant edge arrays (independent of everything): hoisted pre-barrier ----
    {
        const int GL = 2 * LL - 1;           // 1023
        const int NG = BB * GL;              // 8184
        const int SL = 2 * (LL - 2);         // 1020
        const int NS = BB * SL;              // 8160
        float* glb = out + 4 * NTOT * KK;
        #pragma unroll
        for (int sub = 0; sub < 2; sub++) {
            const int gg = (2 * bid + sub) * NTHR + tid;
            if (gg < 2 * NG) {
                const int rr = gg / NG, tt = gg - rr * NG;
                const int b = tt / GL, e = tt - b * GL, off = b * LL;
                int s, d;
                if (e < LL) { s = 0;          d = e; }
                else        { s = e - LL + 1; d = 0; }
                glb[gg] = (float)((rr == 0 ? s : d) + off);
            } else if (gg < 2 * NG + 2 * NS) {
                const int g2 = gg - 2 * NG;
                const int rr = g2 / NS, tt = g2 - rr * NS;
                const int b = tt / SL, e = tt - b * SL, off = b * LL;
                const int hh = LL - 2;
                int s, d;
                if (e < hh) { s = 1 + e;      d = 2 + e; }
                else        { s = e - hh + 2; d = e - hh + 1; }
                glb[2 * NG + g2] = (float)((rr == 0 ? s : d) + off);
            }
        }
    }

    // ---- stage full column smem for this graph (16 groups) ----
    #pragma unroll
    for (int rep = 0; rep < 3; rep++) {
        const int e     = tid + rep * NTHR;      // [0, 3072)
        const int elane = e & 31;
        const int mc    = e >> 5;                // m*6 + ch
        const int ch    = mc % CC;
        const int m     = mc / CC;
        const int j     = (m << 5) | elane;
        const int node  = gbase + j;
        const float x = X[node * 18 + ch * 3 + 0];
        const float y = X[node * 18 + ch * 3 + 1];
        const float z = X[node * 18 + ch * 3 + 2];
        const float sq = x * x + y * y + z * z;
        const float pen = (AP[node * CC + ch] == 0 || S[node] == 0) ? PENF : 0.0f;
        s_col[e] = make_float4(2.0f * x, 2.0f * y, 2.0f * z, sq + pen);
    }
    const float INF = __int_as_float(0x7f800000);
    __syncthreads();

    // ================= Pass 1: triangular d^2 compute, mirrored =================
    // Two triangle tiles per block: t and t+16 (complementary row pairs keep work ~const).
    #pragma unroll
    for (int ti = 0; ti < 2; ti++) {
        const int t = (bid & 15) + 16 * ti;
        const int r = (rw < 8) ? (8 * t + rw) : (496 - 8 * t + rw);
        const int i = gbase + r;

        // row data (warp-uniform); BOS folded into penalty
        float a0[CC], a1[CC], a2[CC], sap[CC];
        {
            const float rpen = (S[i] == 0) ? PENF : 0.0f;
            #pragma unroll
            for (int c = 0; c < CC; c++) {
                a0[c] = X[i * 18 + c * 3 + 0];
                a1[c] = X[i * 18 + c * 3 + 1];
                a2[c] = X[i * 18 + c * 3 + 2];
                const float sq = a0[c] * a0[c] + a1[c] * a1[c] + a2[c] * a2[c];
                sap[c] = sq + ((AP[i * CC + c] == 0) ? PENF : rpen);
            }
        }

        // Exact validated rounding: dot = a0*2x + a1*2y + a2*2z (FMUL,FFMA,FFMA);
        // e = (sap[c] + q.w) - dot (FADD,FSUB). Do not reassociate.
        // sqrt is DEFERRED to output: ordering on fmax(mn,0) bits == ordering on
        // sqrt(fmax(mn,0)) (strictly monotone, tie-exact incl. negative->0 collapse).
        const int Gdiag = r >> 5;
        u32* Mrow = g_M + (size_t)i * LL;
        for (int mf = h; mf <= Gdiag; mf += 2) {
            float mn0 = INF, mn1 = INF, mn2 = INF, mn3 = INF, mn4 = INF, mn5 = INF;
            #pragma unroll
            for (int d = 0; d < CC; d++) {
                const float4 q = s_col[(mf * CC + d) * 32 + lane];
                { const float dot = a0[0]*q.x + a1[0]*q.y + a2[0]*q.z; mn0 = fminf(mn0, (sap[0]+q.w) - dot); }
                { const float dot = a0[1]*q.x + a1[1]*q.y + a2[1]*q.z; mn1 = fminf(mn1, (sap[1]+q.w) - dot); }
                { const float dot = a0[2]*q.x + a1[2]*q.y + a2[2]*q.z; mn2 = fminf(mn2, (sap[2]+q.w) - dot); }
                { const float dot = a0[3]*q.x + a1[3]*q.y + a2[3]*q.z; mn3 = fminf(mn3, (sap[3]+q.w) - dot); }
                { const float dot = a0[4]*q.x + a1[4]*q.y + a2[4]*q.z; mn4 = fminf(mn4, (sap[4]+q.w) - dot); }
                { const float dot = a0[5]*q.x + a1[5]*q.y + a2[5]*q.z; mn5 = fminf(mn5, (sap[5]+q.w) - dot); }
            }
            const float mn = fminf(fminf(fminf(mn0, mn1), fminf(mn2, mn3)), fminf(mn4, mn5));
            const float clamped = fmaxf(mn, 0.0f);
            const u32 bits = (mn >= 1e18f) ? MARKBITS : __float_as_uint(clamped);
            const int j = (mf << 5) | lane;
            Mrow[j] = bits;                                  // coalesced
            if (mf < Gdiag)                                  // strictly-lower: mirror (bitwise symmetric)
                g_M[(size_t)(gbase + j) * LL + r] = bits;
        }
    }

    // ================= Per-graph ticket barrier (16 blocks; replay-safe) ============
    __threadfence();
    __syncthreads();
    if (tid == 0) {
        const u32 ticket = atomicAdd(&g_gcnt[g], 1u);
        const u32 target = (ticket / BPG) * BPG + BPG;       // end of this launch's group of 16
        while ((int)(*(volatile u32*)&g_gcnt[g] - target) < 0) { __nanosleep(64); }
        __threadfence();
    }
    __syncthreads();

    // ================= Pass 2: top-9 selection + outputs ===========================
    #pragma unroll
    for (int sub = 0; sub < 2; sub++) {
        const int vbid = 2 * bid + sub;          // virtual select-block (0..255), same graph
        const int i    = vbid * ROWS_PB + rw;

        // load precomputed d^2 bits (L2-hot), build u64 keys
        const u32* Mrow = g_M + (size_t)i * LL;
        u64 K[CPL];
        #pragma unroll
        for (int m = 0; m < CPL; m++) {
            const int mf = h * CPL + m;
            const int j  = (mf << 5) | lane;
            K[m] = ((u64)Mrow[j] << 32) | (u32)j;
        }

        // lane-local Batcher sort-8 (ascending, u64)
        #define CAS(A, B) { u64 x_ = K[A], y_ = K[B]; const bool sw_ = (y_ < x_); \
                            K[A] = sw_ ? y_ : x_; K[B] = sw_ ? x_ : y_; }
        CAS(0,1) CAS(2,3) CAS(4,5) CAS(6,7)
        CAS(0,2) CAS(1,3) CAS(4,6) CAS(5,7)
        CAS(1,2) CAS(5,6)
        CAS(0,4) CAS(1,5) CAS(2,6) CAS(3,7)
        CAS(2,4) CAS(3,5)
        CAS(1,2) CAS(3,4) CAS(5,6)
        #undef CAS

        // 9-round warp selection: exact u64 min via two u32 redux
        // (low words among candidate lanes are distinct -> lexicographic min)
        #pragma unroll
        for (int m = 0; m < KK; m++) {
            const u32 hi   = (u32)(K[0] >> 32);
            const u32 vhi  = __reduce_min_sync(0xffffffffu, hi);
            const u32 jc   = (hi == vhi) ? (u32)K[0] : 0xffffffffu;
            const u32 vlo  = __reduce_min_sync(0xffffffffu, jc);
            if (jc == vlo) {                    // unique leader: pop winner
                #pragma unroll
                for (int s2 = 0; s2 < CPL - 1; s2++) K[s2] = K[s2 + 1];
                K[CPL - 1] = 0xffffffffffffffffull;
            }
            if (lane == m) s_res[rw][h][m] = ((u64)vhi << 32) | vlo;
        }

        __syncthreads();

        // cross-half merge by rank (u64 keys unique) + output (sqrt applied here)
        if (w < ROWS_PB && lane < 2 * KK) {
            const int row  = w;
            const int side = (lane < KK) ? 0 : 1;
            const int m    = (lane < KK) ? lane : lane - KK;
            const u64 x = s_res[row][side][m];
            int cnt = 0;
            #pragma unroll
            for (int q = 0; q < KK; q++)
                cnt += (s_res[row][side ^ 1][q] < x) ? 1 : 0;
            const int rank = m + cnt;
            if (rank < KK) {
                const int gi  = vbid * ROWS_PB + row;
                const u32 kb  = (u32)(x >> 32);
                const int jl  = (int)(x & 0xffffffffull);
                const bool big = (kb >= MARKBITS);
                // same clamped d^2 value as validated kernel -> bitwise-identical dknn
                const float d = big ? BIGF : sqrtf(__uint_as_float(kb));
                const int  dg = gbase + jl;
                const bool val = (!big) && (SEC[gi] == SEC[dg]);
                const int  NK = NTOT * KK;
                out[0 * NK + gi * KK + rank] = d;
                out[1 * NK + gi * KK + rank] = (float)gi;
                out[2 * NK + gi * KK + rank] = val ? (float)dg : -1.0f;
                out[3 * NK + gi * KK + rank] = val ? 1.0f : 0.0f;
            }
        }
        __syncthreads();   // protect s_res before next sub-iteration
    }
}

extern "C" void kernel_launch(void* const* d_in, const int* in_sizes, int n_in,
                              void* d_out, int out_size)
{
    const float* X   = (const float*)d_in[0];   // [N, C, 3]
    const int*   AP  = (const int*)  d_in[1];   // [N, C]
    const int*   S   = (const int*)  d_in[2];   // [N]
    const int*   SEC = (const int*)  d_in[3];   // [N]
    float* out = (float*)d_out;

    knn_fused_kernel<<<NBLK, NTHR>>>(X, AP, S, SEC, out);
}

// round 16
// speedup vs baseline: 1.0754x; 1.0754x over previous
#include <cuda_runtime.h>
#include <stdint.h>

#define BB 8
#define LL 512
#define CC 6
#define NTOT (BB * LL)     // 4096
#define KK 9
#define BIGF 1e10f
#define PENF 1e19f
#define MARKBITS 0x7F7FFFFFu  // FLT_MAX bits: d^2-space marker for masked entries

#define ROWS_PB 16
#define NBLK 128                // 8 graphs x 16 blocks; all co-resident (1 block/SM)
#define NTHR 1024               // 32 warps
#define CPL 8
#define BPG 16                  // blocks per graph

typedef unsigned long long u64;
typedef unsigned int u32;

// 8MB scratch: clamped-d^2 bits matrix, M[i][j] for i,j in same graph
__device__ u32 g_M[(size_t)NTOT * LL];
// per-graph monotonic ticket counters (never reset; 2^32 % 16 == 0 -> replay-safe)
__device__ u32 g_gcnt[BB];

__global__ __launch_bounds__(NTHR, 1)
void knn_fused_kernel(const float* __restrict__ X,
                      const int*   __restrict__ AP,
                      const int*   __restrict__ S,
                      const int*   __restrict__ SEC,
                      float*       __restrict__ out)
{
    // Column data: [group][ch][lane] float4 {2x, 2y, 2z, |x|^2 + (pad|BOS)*1e19}
    __shared__ float4 s_col[(LL / 32) * CC * 32];          // 48KB
    __shared__ u64 s_res[ROWS_PB][2][KK];

    const int tid  = threadIdx.x;
    const int bid  = blockIdx.x;          // 0..127
    const int lane = tid & 31;
    const int w    = tid >> 5;
    const int rw   = w >> 1;              // warp-pair index (0..15)
    const int h    = w & 1;               // group-parity / column-half
    const int g    = bid >> 4;            // graph
    const int gbase = g << 9;

    // ---- constant edge arrays (independent of everything): hoisted pre-barrier ----
    {
        const int GL = 2 * LL - 1;           // 1023
        const int NG = BB * GL;              // 8184
        const int SL = 2 * (LL - 2);         // 1020
        const int NS = BB * SL;              // 8160
        float* glb = out + 4 * NTOT * KK;
        #pragma unroll
        for (int sub = 0; sub < 2; sub++) {
            const int gg = (2 * bid + sub) * NTHR + tid;
            if (gg < 2 * NG) {
                const int rr = gg / NG, tt = gg - rr * NG;
                const int b = tt / GL, e = tt - b * GL, off = b * LL;
                int s, d;
                if (e < LL) { s = 0;          d = e; }
                else        { s = e - LL + 1; d = 0; }
                glb[gg] = (float)((rr == 0 ? s : d) + off);
            } else if (gg < 2 * NG + 2 * NS) {
                const int g2 = gg - 2 * NG;
                const int rr = g2 / NS, tt = g2 - rr * NS;
                const int b = tt / SL, e = tt - b * SL, off = b * LL;
                const int hh = LL - 2;
                int s, d;
                if (e < hh) { s = 1 + e;      d = 2 + e; }
                else        { s = e - hh + 2; d = e - hh + 1; }
                glb[2 * NG + g2] = (float)((rr == 0 ? s : d) + off);
            }
        }
    }

    // ---- stage full column smem for this graph (16 groups) ----
    #pragma unroll
    for (int rep = 0; rep < 3; rep++) {
        const int e     = tid + rep * NTHR;      // [0, 3072)
        const int elane = e & 31;
        const int mc    = e >> 5;                // m*6 + ch
        const int ch    = mc % CC;
        const int m     = mc / CC;
        const int j     = (m << 5) | elane;
        const int node  = gbase + j;
        const float x = X[node * 18 + ch * 3 + 0];
        const float y = X[node * 18 + ch * 3 + 1];
        const float z = X[node * 18 + ch * 3 + 2];
        const float sq = x * x + y * y + z * z;
        const float pen = (AP[node * CC + ch] == 0 || S[node] == 0) ? PENF : 0.0f;
        s_col[e] = make_float4(2.0f * x, 2.0f * y, 2.0f * z, sq + pen);
    }
    const float INF = __int_as_float(0x7f800000);
    __syncthreads();

    // ================= Pass 1: triangular d^2 compute, mirrored =================
    // Warp-balanced mapping: warp-pair p handles ONE light and ONE heavy row of
    // tile t = (bid&15) + 16*(p>>3): rows 8t+(p&7) and 504-8t+(p&7).
    // Per-warp-pair group total = (T+1)+(16-T) = 17, constant for all warps.
    {
        const int t  = (bid & 15) + 16 * (rw >> 3);
        const int ro = rw & 7;
        #pragma unroll
        for (int half = 0; half < 2; half++) {
            const int r = (half == 0) ? (8 * t + ro) : (504 - 8 * t + ro);
            const int i = gbase + r;

            // row data (warp-uniform); BOS folded into penalty
            float a0[CC], a1[CC], a2[CC], sap[CC];
            {
                const float rpen = (S[i] == 0) ? PENF : 0.0f;
                #pragma unroll
                for (int c = 0; c < CC; c++) {
                    a0[c] = X[i * 18 + c * 3 + 0];
                    a1[c] = X[i * 18 + c * 3 + 1];
                    a2[c] = X[i * 18 + c * 3 + 2];
                    const float sq = a0[c] * a0[c] + a1[c] * a1[c] + a2[c] * a2[c];
                    sap[c] = sq + ((AP[i * CC + c] == 0) ? PENF : rpen);
                }
            }

            // Exact validated rounding: dot = a0*2x + a1*2y + a2*2z (FMUL,FFMA,FFMA);
            // e = (sap[c] + q.w) - dot (FADD,FSUB). Do not reassociate.
            // sqrt deferred to output (monotone, tie-exact).
            const int Gdiag = r >> 5;
            u32* Mrow = g_M + (size_t)i * LL;
            for (int mf = h; mf <= Gdiag; mf += 2) {
                float mn0 = INF, mn1 = INF, mn2 = INF, mn3 = INF, mn4 = INF, mn5 = INF;
                #pragma unroll
                for (int d = 0; d < CC; d++) {
                    const float4 q = s_col[(mf * CC + d) * 32 + lane];
                    { const float dot = a0[0]*q.x + a1[0]*q.y + a2[0]*q.z; mn0 = fminf(mn0, (sap[0]+q.w) - dot); }
                    { const float dot = a0[1]*q.x + a1[1]*q.y + a2[1]*q.z; mn1 = fminf(mn1, (sap[1]+q.w) - dot); }
                    { const float dot = a0[2]*q.x + a1[2]*q.y + a2[2]*q.z; mn2 = fminf(mn2, (sap[2]+q.w) - dot); }
                    { const float dot = a0[3]*q.x + a1[3]*q.y + a2[3]*q.z; mn3 = fminf(mn3, (sap[3]+q.w) - dot); }
                    { const float dot = a0[4]*q.x + a1[4]*q.y + a2[4]*q.z; mn4 = fminf(mn4, (sap[4]+q.w) - dot); }
                    { const float dot = a0[5]*q.x + a1[5]*q.y + a2[5]*q.z; mn5 = fminf(mn5, (sap[5]+q.w) - dot); }
                }
                const float mn = fminf(fminf(fminf(mn0, mn1), fminf(mn2, mn3)), fminf(mn4, mn5));
                const float clamped = fmaxf(mn, 0.0f);
                const u32 bits = (mn >= 1e18f) ? MARKBITS : __float_as_uint(clamped);
                const int j = (mf << 5) | lane;
                Mrow[j] = bits;                                  // coalesced
                if (mf < Gdiag)                                  // strictly-lower: mirror (bitwise symmetric)
                    g_M[(size_t)(gbase + j) * LL + r] = bits;
            }
        }
    }

    // ================= Per-graph ticket barrier (16 blocks; replay-safe) ============
    __threadfence();
    __syncthreads();
    if (tid == 0) {
        const u32 ticket = atomicAdd(&g_gcnt[g], 1u);
        const u32 target = (ticket / BPG) * BPG + BPG;       // end of this launch's group of 16
        while ((int)(*(volatile u32*)&g_gcnt[g] - target) < 0) { __nanosleep(64); }
        __threadfence();
    }
    __syncthreads();

    // ================= Pass 2: top-9 selection + outputs ===========================
    #pragma unroll
    for (int sub = 0; sub < 2; sub++) {
        const int vbid = 2 * bid + sub;          // virtual select-block (0..255), same graph
        const int i    = vbid * ROWS_PB + rw;

        // load precomputed d^2 bits (L2-hot), build u64 keys
        const u32* Mrow = g_M + (size_t)i * LL;
        u64 K[CPL];
        #pragma unroll
        for (int m = 0; m < CPL; m++) {
            const int mf = h * CPL + m;
            const int j  = (mf << 5) | lane;
            K[m] = ((u64)Mrow[j] << 32) | (u32)j;
        }

        // lane-local Batcher sort-8 (ascending, u64)
        #define CAS(A, B) { u64 x_ = K[A], y_ = K[B]; const bool sw_ = (y_ < x_); \
                            K[A] = sw_ ? y_ : x_; K[B] = sw_ ? x_ : y_; }
        CAS(0,1) CAS(2,3) CAS(4,5) CAS(6,7)
        CAS(0,2) CAS(1,3) CAS(4,6) CAS(5,7)
        CAS(1,2) CAS(5,6)
        CAS(0,4) CAS(1,5) CAS(2,6) CAS(3,7)
        CAS(2,4) CAS(3,5)
        CAS(1,2) CAS(3,4) CAS(5,6)
        #undef CAS

        // 9-round warp selection: exact u64 min via two u32 redux
        // (low words among candidate lanes are distinct -> lexicographic min)
        #pragma unroll
        for (int m = 0; m < KK; m++) {
            const u32 hi   = (u32)(K[0] >> 32);
            const u32 vhi  = __reduce_min_sync(0xffffffffu, hi);
            const u32 jc   = (hi == vhi) ? (u32)K[0] : 0xffffffffu;
            const u32 vlo  = __reduce_min_sync(0xffffffffu, jc);
            if (jc == vlo) {                    // unique leader: pop winner
                #pragma unroll
                for (int s2 = 0; s2 < CPL - 1; s2++) K[s2] = K[s2 + 1];
                K[CPL - 1] = 0xffffffffffffffffull;
            }
            if (lane == m) s_res[rw][h][m] = ((u64)vhi << 32) | vlo;
        }

        __syncthreads();

        // cross-half merge by rank (u64 keys unique) + output (sqrt applied here)
        if (w < ROWS_PB && lane < 2 * KK) {
            const int row  = w;
            const int side = (lane < KK) ? 0 : 1;
            const int m    = (lane < KK) ? lane : lane - KK;
            const u64 x = s_res[row][side][m];
            int cnt = 0;
            #pragma unroll
            for (int q = 0; q < KK; q++)
                cnt += (s_res[row][side ^ 1][q] < x) ? 1 : 0;
            const int rank = m + cnt;
            if (rank < KK) {
                const int gi  = vbid * ROWS_PB + row;
                const u32 kb  = (u32)(x >> 32);
                const int jl  = (int)(x & 0xffffffffull);
                const bool big = (kb >= MARKBITS);
                // same clamped d^2 value as validated kernel -> bitwise-identical dknn
                const float d = big ? BIGF : sqrtf(__uint_as_float(kb));
                const int  dg = gbase + jl;
                const bool val = (!big) && (SEC[gi] == SEC[dg]);
                const int  NK = NTOT * KK;
                out[0 * NK + gi * KK + rank] = d;
                out[1 * NK + gi * KK + rank] = (float)gi;
                out[2 * NK + gi * KK + rank] = val ? (float)dg : -1.0f;
                out[3 * NK + gi * KK + rank] = val ? 1.0f : 0.0f;
            }
        }
        __syncthreads();   // protect s_res before next sub-iteration
    }
}

extern "C" void kernel_launch(void* const* d_in, const int* in_sizes, int n_in,
                              void* d_out, int out_size)
{
    const float* X   = (const float*)d_in[0];   // [N, C, 3]
    const int*   AP  = (const int*)  d_in[1];   // [N, C]
    const int*   S   = (const int*)  d_in[2];   // [N]
    const int*   SEC = (const int*)  d_in[3];   // [N]
    float* out = (float*)d_out;

    knn_fused_kernel<<<NBLK, NTHR>>>(X, AP, S, SEC, out);
}